// round 13
// baseline (speedup 1.0000x reference)
#include <cuda_runtime.h>
#include <cuda_bf16.h>
#include <cstdint>

// Problem constants (BuseE): N_ENT=200000, N_REL=500, DIM=64, B=1024, NC=1024
#define N_ENT 200000
#define BQ    1024
#define NC    1024
#define MARGIN 9.0f
#define EPS 1e-15f

#define TAIL_BLOCKS (N_ENT / 64)   // 3125 (64 rows / 256-thr block, 4 lanes/row)
#define HEAD_BLOCKS (BQ / 8)       // 128

// ---------------- device scratch (allocation-free) ----------------
// per-entity 128B line: [0,64) = 64 x int8 dims; [64,80) = float4 meta
// meta = { t2, log(max(1-t2,eps)), bias_tail, sc }
__device__ uint4 g_row[N_ENT * 8];          // 25.6 MB
// per-b quantized head: 64 x int8 = 16 words
__device__ unsigned g_headq[BQ * 16];
// per-b: { A, sig, hh, 2*sh/(127*127) }
__device__ float4 g_rowc[BQ];

// ---------------- fast math helpers -------------------------------
__device__ __forceinline__ float tanh_approx(float x) {
    float r;
    asm("tanh.approx.f32 %0, %1;" : "=f"(r) : "f"(x));
    return r;
}

__device__ __forceinline__ float wsum32(float v) {
    #pragma unroll
    for (int m = 16; m; m >>= 1) v += __shfl_xor_sync(0xffffffffu, v, m);
    return v;
}
__device__ __forceinline__ float wmax32(float v) {
    #pragma unroll
    for (int m = 16; m; m >>= 1)
        v = fmaxf(v, __shfl_xor_sync(0xffffffffu, v, m));
    return v;
}

// ---------------- head transform primitives (warp-per-row) --------
__device__ __forceinline__ float2 expmap0_w(float2 v) {
    float n2   = wsum32(v.x * v.x + v.y * v.y);
    float rinv = rsqrtf(fmaxf(n2, 1e-36f));
    float un   = fmaxf(n2 * rinv, EPS);
    float f    = tanh_approx(un) * rinv;
    return make_float2(f * v.x, f * v.y);
}

__device__ __forceinline__ float2 mobius_w(float2 x, float2 y) {
    float x2 = wsum32(x.x * x.x + x.y * x.y);
    float y2 = wsum32(y.x * y.x + y.y * y.y);
    float xy = wsum32(x.x * y.x + x.y * y.y);
    float a   = 1.f + 2.f * xy + y2;
    float bq  = 1.f - x2;
    float inv = 1.f / fmaxf(1.f + 2.f * xy + x2 * y2, EPS);
    return make_float2((a * x.x + bq * y.x) * inv,
                       (a * x.y + bq * y.y) * inv);
}

__device__ __forceinline__ unsigned pack4(float a, float b, float c, float d,
                                          float fi) {
    int q0 = __float2int_rn(a * fi);
    int q1 = __float2int_rn(b * fi);
    int q2 = __float2int_rn(c * fi);
    int q3 = __float2int_rn(d * fi);
    return (q0 & 0xFF) | ((q1 & 0xFF) << 8) | ((q2 & 0xFF) << 16)
         | ((unsigned)(q3 & 0xFF) << 24);
}

// ---------------- fused prep kernel -------------------------------
__global__ void __launch_bounds__(256) prep_kernel(
    const int* __restrict__ u_idx, const int* __restrict__ r_idx,
    const float* __restrict__ emb, const float* __restrict__ rel_diag,
    const float* __restrict__ rb1, const float* __restrict__ rb2,
    const float* __restrict__ bias_head, const float* __restrict__ bias_tail,
    const float* __restrict__ sigma)
{
    if (blockIdx.x < TAIL_BLOCKS) {
        // ---- tail path: 4 lanes per entity row (64 rows / block) ----
        int row = blockIdx.x * 64 + (threadIdx.x >> 2);
        int s   = threadIdx.x & 3;        // lane covers dims [s*16, s*16+16)

        const float4* e4 = reinterpret_cast<const float4*>(emb) + (size_t)row * 16;
        float4 a = e4[s * 4 + 0];
        float4 b = e4[s * 4 + 1];
        float4 c = e4[s * 4 + 2];
        float4 d = e4[s * 4 + 3];

        float p = a.x*a.x + a.y*a.y + a.z*a.z + a.w*a.w
                + b.x*b.x + b.y*b.y + b.z*b.z + b.w*b.w
                + c.x*c.x + c.y*c.y + c.z*c.z + c.w*c.w
                + d.x*d.x + d.y*d.y + d.z*d.z + d.w*d.w;
        float am = fmaxf(fmaxf(fmaxf(fabsf(a.x), fabsf(a.y)),
                               fmaxf(fabsf(a.z), fabsf(a.w))),
                   fmaxf(fmaxf(fabsf(b.x), fabsf(b.y)),
                         fmaxf(fabsf(b.z), fabsf(b.w))));
        am = fmaxf(am, fmaxf(fmaxf(fabsf(c.x), fabsf(c.y)),
                             fmaxf(fabsf(c.z), fabsf(c.w))));
        am = fmaxf(am, fmaxf(fmaxf(fabsf(d.x), fabsf(d.y)),
                             fmaxf(fabsf(d.z), fabsf(d.w))));
        #pragma unroll
        for (int m = 2; m; m >>= 1) {
            p  += __shfl_xor_sync(0xffffffffu, p, m);
            am  = fmaxf(am, __shfl_xor_sync(0xffffffffu, am, m));
        }

        float rinv = rsqrtf(fmaxf(p, 1e-36f));
        float un   = fmaxf(p * rinv, EPS);
        float f    = tanh_approx(un) * rinv;   // tail = f * u
        float sc   = f * am;                   // max |tail_i|
        float fi   = 127.f * f / fmaxf(sc, 1e-30f);

        uint4 o;
        o.x = pack4(a.x, a.y, a.z, a.w, fi);
        o.y = pack4(b.x, b.y, b.z, b.w, fi);
        o.z = pack4(c.x, c.y, c.z, c.w, fi);
        o.w = pack4(d.x, d.y, d.z, d.w, fi);
        g_row[(size_t)row * 8 + s] = o;

        if (s == 0) {
            float t  = tanh_approx(un);
            float t2 = t * t;
            float4 meta = make_float4(t2, __logf(fmaxf(1.f - t2, EPS)),
                                      bias_tail[row], sc);
            g_row[(size_t)row * 8 + 4] = *reinterpret_cast<uint4*>(&meta);
        }
    } else {
        // ---- head path: 1 warp per b-row (8 rows / block) ----
        int b    = (blockIdx.x - TAIL_BLOCKS) * 8 + (threadIdx.x >> 5);
        int lane = threadIdx.x & 31;
        int u = u_idx[b];
        int r = r_idx[b];

        float2 h  = expmap0_w(reinterpret_cast<const float2*>(emb + (size_t)u * 64)[lane]);
        float2 y1 = expmap0_w(reinterpret_cast<const float2*>(rb1 + (size_t)r * 64)[lane]);
        h = mobius_w(h, y1);

        float2 g  = reinterpret_cast<const float2*>(rel_diag + (size_t)r * 64)[lane];
        float gri = rsqrtf(fmaxf(g.x * g.x + g.y * g.y, 1e-36f));
        float gx = g.x * gri, gy = g.y * gri;
        float2 rot = make_float2(gx * h.x - gy * h.y, gy * h.x + gx * h.y);

        float2 y2 = expmap0_w(reinterpret_cast<const float2*>(rb2 + (size_t)r * 64)[lane]);
        h = mobius_w(rot, y2);

        float hh = wsum32(h.x * h.x + h.y * h.y);
        float sh = fmaxf(wmax32(fmaxf(fabsf(h.x), fabsf(h.y))), 1e-30f);
        float inv = 127.f / sh;

        int q0 = __float2int_rn(h.x * inv);
        int q1 = __float2int_rn(h.y * inv);
        unsigned pk = (q0 & 0xFF) | ((q1 & 0xFF) << 8);
        unsigned other = __shfl_xor_sync(0xffffffffu, pk, 1);
        if ((lane & 1) == 0)
            g_headq[b * 16 + (lane >> 1)] = (pk & 0xFFFFu) | (other << 16);

        if (lane == 0) {
            float sg = 1.f / (1.f + __expf(-sigma[r]));
            float A  = MARGIN + bias_head[u]
                     + (1.f - sg) * __logf(fmaxf(1.f - hh, EPS));
            g_rowc[b] = make_float4(A, sg, hh, 2.f * sh / 16129.f);
        }
    }
}

// ---------------- scoring (hot loop) ------------------------------
// 4-lane group per element: every lane carries 16 dims (uint4), so all
// gather/dp4a warp-instructions run at 100% lane utilization.
// Warp owns 16 candidates as 2 sets of 8:
//   - 16 idx loaded coalesced (1 LDG.32), broadcast per-set via SHFL.IDX
//   - dims: 1 LDG.128/set (8 lines)
//   - meta: predicated LDG.128 on group-lane-0, SAME 128B line (L1 merge)
//   - 4 dp4a/lane, 2-level shfl reduce, epilogue+STG.32 on group-lane-0
__global__ void __launch_bounds__(128) score_kernel(
    const int* __restrict__ v_idx, float* __restrict__ out)
{
    int w    = threadIdx.x >> 5;
    int gw   = blockIdx.x * 4 + w;       // global warp id
    int b    = gw >> 6;                  // b-row (64 warps per row)
    int seg  = gw & 63;
    int lane = threadIdx.x & 31;
    int g    = lane >> 2;                // group 0..7
    int q    = lane & 3;                 // slot in group

    int cbase = seg * 16;
    const int* vrow = v_idx + b * NC;
    float*     orow = out + b * NC;

    // 16 candidate indices, coalesced (lanes 16..31 redundant, harmless)
    int V = __ldg(vrow + cbase + (lane & 15));

    // head chunk for this slot
    uint4 hq = reinterpret_cast<const uint4*>(g_headq)[b * 4 + q];
    float4 rc = g_rowc[b];               // {A, sig, hh, 2*sh/127^2}

    const char* base = reinterpret_cast<const char*>(g_row);
    unsigned so = (unsigned)q * 16u;

    // ---- flat address + load phase (both sets) ----
    unsigned off0 = (unsigned)__shfl_sync(0xffffffffu, V, g)     * 128u;
    unsigned off1 = (unsigned)__shfl_sync(0xffffffffu, V, 8 + g) * 128u;

    uint4 d0 = *reinterpret_cast<const uint4*>(base + (off0 + so));
    uint4 d1 = *reinterpret_cast<const uint4*>(base + (off1 + so));

    float4 m0 = make_float4(0.f, 0.f, 0.f, 0.f);
    float4 m1 = make_float4(0.f, 0.f, 0.f, 0.f);
    if (q == 0) {
        m0 = *reinterpret_cast<const float4*>(base + (off0 + 64u));
        m1 = *reinterpret_cast<const float4*>(base + (off1 + 64u));
    }

    // ---- integer dots (all lanes productive) ----
    int I0 = 0, I1 = 0;
    I0 = __dp4a((int)d0.x, (int)hq.x, I0);
    I0 = __dp4a((int)d0.y, (int)hq.y, I0);
    I0 = __dp4a((int)d0.z, (int)hq.z, I0);
    I0 = __dp4a((int)d0.w, (int)hq.w, I0);
    I1 = __dp4a((int)d1.x, (int)hq.x, I1);
    I1 = __dp4a((int)d1.y, (int)hq.y, I1);
    I1 = __dp4a((int)d1.z, (int)hq.z, I1);
    I1 = __dp4a((int)d1.w, (int)hq.w, I1);

    // ---- 2-level group reduce ----
    I0 += __shfl_xor_sync(0xffffffffu, I0, 1);
    I1 += __shfl_xor_sync(0xffffffffu, I1, 1);
    I0 += __shfl_xor_sync(0xffffffffu, I0, 2);
    I1 += __shfl_xor_sync(0xffffffffu, I1, 2);

    // ---- epilogue + stores on group-lane-0 (8 lanes, 32B coalesced) ----
    if (q == 0) {
        float n0 = fmaxf(rc.z + m0.x - rc.w * m0.w * (float)I0, EPS);
        float n1 = fmaxf(rc.z + m1.x - rc.w * m1.w * (float)I1, EPS);
        orow[cbase + g]     = rc.x + fmaf(rc.y, m0.y, m0.z) - __logf(n0);
        orow[cbase + 8 + g] = rc.x + fmaf(rc.y, m1.y, m1.z) - __logf(n1);
    }
}

// ---------------- launch ------------------------------------------
extern "C" void kernel_launch(void* const* d_in, const int* in_sizes, int n_in,
                              void* d_out, int out_size)
{
    const int*   u_idx     = (const int*)  d_in[0];
    const int*   r_idx     = (const int*)  d_in[1];
    const int*   v_idx     = (const int*)  d_in[2];
    const float* emb       = (const float*)d_in[3];
    const float* rel_diag  = (const float*)d_in[4];
    const float* rb1       = (const float*)d_in[5];
    const float* rb2       = (const float*)d_in[6];
    const float* bias_head = (const float*)d_in[7];
    const float* bias_tail = (const float*)d_in[8];
    const float* sigma     = (const float*)d_in[9];
    float* out = (float*)d_out;

    prep_kernel<<<TAIL_BLOCKS + HEAD_BLOCKS, 256>>>(
        u_idx, r_idx, emb, rel_diag, rb1, rb2, bias_head, bias_tail, sigma);
    // 1M elements / (4 warps * 16 elem) = 16384 blocks
    score_kernel<<<(BQ * NC) / 64, 128>>>(v_idx, out);
}

// round 15
// speedup vs baseline: 1.0848x; 1.0848x over previous
#include <cuda_runtime.h>
#include <cuda_bf16.h>
#include <cstdint>

// Problem constants (BuseE): N_ENT=200000, N_REL=500, DIM=64, B=1024, NC=1024
#define N_ENT 200000
#define BQ    1024
#define NC    1024
#define MARGIN 9.0f
#define EPS 1e-15f

#define TAIL_BLOCKS (N_ENT / 64)   // 3125 (64 rows / 256-thr block, 4 lanes/row)
#define HEAD_BLOCKS (BQ / 8)       // 128

// ---------------- device scratch (allocation-free) ----------------
// per-entity 128B line: [0,64) = 64 x int8 dims; [64,80) = float4 meta
// meta = { t2, log(max(1-t2,eps)), bias_tail, sc }
__device__ uint4 g_row[N_ENT * 8];          // 25.6 MB
// per-b quantized head: 64 x int8 = 16 words
__device__ unsigned g_headq[BQ * 16];
// per-b: { A, sig, hh, 2*sh/(127*127) }
__device__ float4 g_rowc[BQ];

// ---------------- fast math helpers -------------------------------
__device__ __forceinline__ float tanh_approx(float x) {
    float r;
    asm("tanh.approx.f32 %0, %1;" : "=f"(r) : "f"(x));
    return r;
}

// streaming float4 load (L2 evict-first: don't pollute L2 against g_row)
__device__ __forceinline__ float4 ldcs4(const float4* p) {
    return __ldcs(p);
}

__device__ __forceinline__ float wsum32(float v) {
    #pragma unroll
    for (int m = 16; m; m >>= 1) v += __shfl_xor_sync(0xffffffffu, v, m);
    return v;
}
__device__ __forceinline__ float wmax32(float v) {
    #pragma unroll
    for (int m = 16; m; m >>= 1)
        v = fmaxf(v, __shfl_xor_sync(0xffffffffu, v, m));
    return v;
}

// ---------------- head transform primitives (warp-per-row) --------
__device__ __forceinline__ float2 expmap0_w(float2 v) {
    float n2   = wsum32(v.x * v.x + v.y * v.y);
    float rinv = rsqrtf(fmaxf(n2, 1e-36f));
    float un   = fmaxf(n2 * rinv, EPS);
    float f    = tanh_approx(un) * rinv;
    return make_float2(f * v.x, f * v.y);
}

__device__ __forceinline__ float2 mobius_w(float2 x, float2 y) {
    float x2 = wsum32(x.x * x.x + x.y * x.y);
    float y2 = wsum32(y.x * y.x + y.y * y.y);
    float xy = wsum32(x.x * y.x + x.y * y.y);
    float a   = 1.f + 2.f * xy + y2;
    float bq  = 1.f - x2;
    float inv = 1.f / fmaxf(1.f + 2.f * xy + x2 * y2, EPS);
    return make_float2((a * x.x + bq * y.x) * inv,
                       (a * x.y + bq * y.y) * inv);
}

__device__ __forceinline__ unsigned pack4(float a, float b, float c, float d,
                                          float fi) {
    int q0 = __float2int_rn(a * fi);
    int q1 = __float2int_rn(b * fi);
    int q2 = __float2int_rn(c * fi);
    int q3 = __float2int_rn(d * fi);
    return (q0 & 0xFF) | ((q1 & 0xFF) << 8) | ((q2 & 0xFF) << 16)
         | ((unsigned)(q3 & 0xFF) << 24);
}

// ---------------- fused prep kernel -------------------------------
__global__ void __launch_bounds__(256) prep_kernel(
    const int* __restrict__ u_idx, const int* __restrict__ r_idx,
    const float* __restrict__ emb, const float* __restrict__ rel_diag,
    const float* __restrict__ rb1, const float* __restrict__ rb2,
    const float* __restrict__ bias_head, const float* __restrict__ bias_tail,
    const float* __restrict__ sigma)
{
    if (blockIdx.x < TAIL_BLOCKS) {
        // ---- tail path: 4 lanes per entity row (64 rows / block) ----
        int row = blockIdx.x * 64 + (threadIdx.x >> 2);
        int s   = threadIdx.x & 3;        // lane covers dims [s*16, s*16+16)

        const float4* e4 = reinterpret_cast<const float4*>(emb) + (size_t)row * 16;
        float4 a = ldcs4(e4 + s * 4 + 0);   // evict-first: keep L2 for g_row
        float4 b = ldcs4(e4 + s * 4 + 1);
        float4 c = ldcs4(e4 + s * 4 + 2);
        float4 d = ldcs4(e4 + s * 4 + 3);

        float p = a.x*a.x + a.y*a.y + a.z*a.z + a.w*a.w
                + b.x*b.x + b.y*b.y + b.z*b.z + b.w*b.w
                + c.x*c.x + c.y*c.y + c.z*c.z + c.w*c.w
                + d.x*d.x + d.y*d.y + d.z*d.z + d.w*d.w;
        float am = fmaxf(fmaxf(fmaxf(fabsf(a.x), fabsf(a.y)),
                               fmaxf(fabsf(a.z), fabsf(a.w))),
                   fmaxf(fmaxf(fabsf(b.x), fabsf(b.y)),
                         fmaxf(fabsf(b.z), fabsf(b.w))));
        am = fmaxf(am, fmaxf(fmaxf(fabsf(c.x), fabsf(c.y)),
                             fmaxf(fabsf(c.z), fabsf(c.w))));
        am = fmaxf(am, fmaxf(fmaxf(fabsf(d.x), fabsf(d.y)),
                             fmaxf(fabsf(d.z), fabsf(d.w))));
        #pragma unroll
        for (int m = 2; m; m >>= 1) {
            p  += __shfl_xor_sync(0xffffffffu, p, m);
            am  = fmaxf(am, __shfl_xor_sync(0xffffffffu, am, m));
        }

        float rinv = rsqrtf(fmaxf(p, 1e-36f));
        float un   = fmaxf(p * rinv, EPS);
        float f    = tanh_approx(un) * rinv;   // tail = f * u
        float sc   = f * am;                   // max |tail_i|
        float fi   = 127.f * f / fmaxf(sc, 1e-30f);

        uint4 o;
        o.x = pack4(a.x, a.y, a.z, a.w, fi);
        o.y = pack4(b.x, b.y, b.z, b.w, fi);
        o.z = pack4(c.x, c.y, c.z, c.w, fi);
        o.w = pack4(d.x, d.y, d.z, d.w, fi);
        g_row[(size_t)row * 8 + s] = o;

        if (s == 0) {
            float t  = tanh_approx(un);
            float t2 = t * t;
            float4 meta = make_float4(t2, __logf(fmaxf(1.f - t2, EPS)),
                                      __ldcs(bias_tail + row), sc);
            g_row[(size_t)row * 8 + 4] = *reinterpret_cast<uint4*>(&meta);
        }
    } else {
        // ---- head path: 1 warp per b-row (8 rows / block) ----
        int b    = (blockIdx.x - TAIL_BLOCKS) * 8 + (threadIdx.x >> 5);
        int lane = threadIdx.x & 31;
        int u = u_idx[b];
        int r = r_idx[b];

        float2 h  = expmap0_w(reinterpret_cast<const float2*>(emb + (size_t)u * 64)[lane]);
        float2 y1 = expmap0_w(reinterpret_cast<const float2*>(rb1 + (size_t)r * 64)[lane]);
        h = mobius_w(h, y1);

        float2 g  = reinterpret_cast<const float2*>(rel_diag + (size_t)r * 64)[lane];
        float gri = rsqrtf(fmaxf(g.x * g.x + g.y * g.y, 1e-36f));
        float gx = g.x * gri, gy = g.y * gri;
        float2 rot = make_float2(gx * h.x - gy * h.y, gy * h.x + gx * h.y);

        float2 y2 = expmap0_w(reinterpret_cast<const float2*>(rb2 + (size_t)r * 64)[lane]);
        h = mobius_w(rot, y2);

        float hh = wsum32(h.x * h.x + h.y * h.y);
        float sh = fmaxf(wmax32(fmaxf(fabsf(h.x), fabsf(h.y))), 1e-30f);
        float inv = 127.f / sh;

        int q0 = __float2int_rn(h.x * inv);
        int q1 = __float2int_rn(h.y * inv);
        unsigned pk = (q0 & 0xFF) | ((q1 & 0xFF) << 8);
        unsigned other = __shfl_xor_sync(0xffffffffu, pk, 1);
        if ((lane & 1) == 0)
            g_headq[b * 16 + (lane >> 1)] = (pk & 0xFFFFu) | (other << 16);

        if (lane == 0) {
            float sg = 1.f / (1.f + __expf(-sigma[r]));
            float A  = MARGIN + bias_head[u]
                     + (1.f - sg) * __logf(fmaxf(1.f - hh, EPS));
            g_rowc[b] = make_float4(A, sg, hh, 2.f * sh / 16129.f);
        }
    }
}

// ---------------- scoring (hot loop) ------------------------------
// 4-lane group per element (every lane carries 16 dims -> 100% lane
// utilization on gathers/dp4a). Warp owns 16 candidates as 2 sets of 8.
// Idx loaded DIRECTLY per group (4-lane broadcast, 1 wavefront) — no
// SHFL in the idx->gather chain. Meta via predicated LDG.128 on group
// lane 0 from the same 128B line. 2-level shfl reduce, STG.32 epilogue.
__global__ void __launch_bounds__(128) score_kernel(
    const int* __restrict__ v_idx, float* __restrict__ out)
{
    int w    = threadIdx.x >> 5;
    int gw   = blockIdx.x * 4 + w;       // global warp id
    int b    = gw >> 6;                  // b-row (64 warps per row)
    int seg  = gw & 63;
    int lane = threadIdx.x & 31;
    int g    = lane >> 2;                // group 0..7
    int q    = lane & 3;                 // slot in group

    int cbase = seg * 16;
    const int* vrow = v_idx + b * NC;
    float*     orow = out + b * NC;

    // ---- direct idx loads (broadcast within group; no shfl chain) ----
    int v0 = __ldg(vrow + cbase + g);
    int v1 = __ldg(vrow + cbase + 8 + g);

    // head chunk for this slot
    uint4 hq = reinterpret_cast<const uint4*>(g_headq)[b * 4 + q];
    float4 rc = g_rowc[b];               // {A, sig, hh, 2*sh/127^2}

    const char* base = reinterpret_cast<const char*>(g_row);
    unsigned so = (unsigned)q * 16u;
    unsigned off0 = (unsigned)v0 * 128u;
    unsigned off1 = (unsigned)v1 * 128u;

    // ---- flat load phase (both sets) ----
    uint4 d0 = *reinterpret_cast<const uint4*>(base + (off0 + so));
    uint4 d1 = *reinterpret_cast<const uint4*>(base + (off1 + so));

    float4 m0 = make_float4(0.f, 0.f, 0.f, 0.f);
    float4 m1 = make_float4(0.f, 0.f, 0.f, 0.f);
    if (q == 0) {
        m0 = *reinterpret_cast<const float4*>(base + (off0 + 64u));
        m1 = *reinterpret_cast<const float4*>(base + (off1 + 64u));
    }

    // ---- integer dots (all lanes productive) ----
    int I0 = 0, I1 = 0;
    I0 = __dp4a((int)d0.x, (int)hq.x, I0);
    I0 = __dp4a((int)d0.y, (int)hq.y, I0);
    I0 = __dp4a((int)d0.z, (int)hq.z, I0);
    I0 = __dp4a((int)d0.w, (int)hq.w, I0);
    I1 = __dp4a((int)d1.x, (int)hq.x, I1);
    I1 = __dp4a((int)d1.y, (int)hq.y, I1);
    I1 = __dp4a((int)d1.z, (int)hq.z, I1);
    I1 = __dp4a((int)d1.w, (int)hq.w, I1);

    // ---- 2-level group reduce ----
    I0 += __shfl_xor_sync(0xffffffffu, I0, 1);
    I1 += __shfl_xor_sync(0xffffffffu, I1, 1);
    I0 += __shfl_xor_sync(0xffffffffu, I0, 2);
    I1 += __shfl_xor_sync(0xffffffffu, I1, 2);

    // ---- epilogue + stores on group-lane-0 (8 lanes, 32B coalesced) ----
    if (q == 0) {
        float n0 = fmaxf(rc.z + m0.x - rc.w * m0.w * (float)I0, EPS);
        float n1 = fmaxf(rc.z + m1.x - rc.w * m1.w * (float)I1, EPS);
        orow[cbase + g]     = rc.x + fmaf(rc.y, m0.y, m0.z) - __logf(n0);
        orow[cbase + 8 + g] = rc.x + fmaf(rc.y, m1.y, m1.z) - __logf(n1);
    }
}

// ---------------- launch ------------------------------------------
extern "C" void kernel_launch(void* const* d_in, const int* in_sizes, int n_in,
                              void* d_out, int out_size)
{
    const int*   u_idx     = (const int*)  d_in[0];
    const int*   r_idx     = (const int*)  d_in[1];
    const int*   v_idx     = (const int*)  d_in[2];
    const float* emb       = (const float*)d_in[3];
    const float* rel_diag  = (const float*)d_in[4];
    const float* rb1       = (const float*)d_in[5];
    const float* rb2       = (const float*)d_in[6];
    const float* bias_head = (const float*)d_in[7];
    const float* bias_tail = (const float*)d_in[8];
    const float* sigma     = (const float*)d_in[9];
    float* out = (float*)d_out;

    prep_kernel<<<TAIL_BLOCKS + HEAD_BLOCKS, 256>>>(
        u_idx, r_idx, emb, rel_diag, rb1, rb2, bias_head, bias_tail, sigma);
    // 1M elements / (4 warps * 16 elem) = 16384 blocks
    score_kernel<<<(BQ * NC) / 64, 128>>>(v_idx, out);
}

// round 17
// speedup vs baseline: 1.1101x; 1.0234x over previous
#include <cuda_runtime.h>
#include <cuda_bf16.h>
#include <cstdint>

// Problem constants (BuseE): N_ENT=200000, N_REL=500, DIM=64, B=1024, NC=1024
#define N_ENT 200000
#define BQ    1024
#define NC    1024
#define MARGIN 9.0f
#define EPS 1e-15f

#define TAIL_BLOCKS (N_ENT / 64)   // 3125 (64 rows / 256-thr block, 4 lanes/row)
#define HEAD_BLOCKS (BQ / 8)       // 128

// ---------------- device scratch (allocation-free) ----------------
// per-entity 128B line: [0,64) = 64 x int8 dims; [64,80) = float4 meta
// meta = { t2, log(max(1-t2,eps)), bias_tail, sc }
__device__ uint4 g_row[N_ENT * 8];          // 25.6 MB
// per-b quantized head: 64 x int8 = 16 words
__device__ unsigned g_headq[BQ * 16];
// per-b: { A, sig, hh, 2*sh/(127*127) }
__device__ float4 g_rowc[BQ];

// ---------------- fast math helpers -------------------------------
__device__ __forceinline__ float tanh_approx(float x) {
    float r;
    asm("tanh.approx.f32 %0, %1;" : "=f"(r) : "f"(x));
    return r;
}

__device__ __forceinline__ float4 ldcs4(const float4* p) {
    return __ldcs(p);
}

__device__ __forceinline__ float wsum32(float v) {
    #pragma unroll
    for (int m = 16; m; m >>= 1) v += __shfl_xor_sync(0xffffffffu, v, m);
    return v;
}
__device__ __forceinline__ float wmax32(float v) {
    #pragma unroll
    for (int m = 16; m; m >>= 1)
        v = fmaxf(v, __shfl_xor_sync(0xffffffffu, v, m));
    return v;
}

// ---------------- head transform primitives (warp-per-row) --------
__device__ __forceinline__ float2 expmap0_w(float2 v) {
    float n2   = wsum32(v.x * v.x + v.y * v.y);
    float rinv = rsqrtf(fmaxf(n2, 1e-36f));
    float un   = fmaxf(n2 * rinv, EPS);
    float f    = tanh_approx(un) * rinv;
    return make_float2(f * v.x, f * v.y);
}

__device__ __forceinline__ float2 mobius_w(float2 x, float2 y) {
    float x2 = wsum32(x.x * x.x + x.y * x.y);
    float y2 = wsum32(y.x * y.x + y.y * y.y);
    float xy = wsum32(x.x * y.x + x.y * y.y);
    float a   = 1.f + 2.f * xy + y2;
    float bq  = 1.f - x2;
    float inv = 1.f / fmaxf(1.f + 2.f * xy + x2 * y2, EPS);
    return make_float2((a * x.x + bq * y.x) * inv,
                       (a * x.y + bq * y.y) * inv);
}

__device__ __forceinline__ unsigned pack4(float a, float b, float c, float d,
                                          float fi) {
    int q0 = __float2int_rn(a * fi);
    int q1 = __float2int_rn(b * fi);
    int q2 = __float2int_rn(c * fi);
    int q3 = __float2int_rn(d * fi);
    return (q0 & 0xFF) | ((q1 & 0xFF) << 8) | ((q2 & 0xFF) << 16)
         | ((unsigned)(q3 & 0xFF) << 24);
}

// ---------------- fused prep kernel -------------------------------
__global__ void __launch_bounds__(256) prep_kernel(
    const int* __restrict__ u_idx, const int* __restrict__ r_idx,
    const float* __restrict__ emb, const float* __restrict__ rel_diag,
    const float* __restrict__ rb1, const float* __restrict__ rb2,
    const float* __restrict__ bias_head, const float* __restrict__ bias_tail,
    const float* __restrict__ sigma)
{
    if (blockIdx.x < TAIL_BLOCKS) {
        // ---- tail path: 4 lanes per entity row (64 rows / block) ----
        int row = blockIdx.x * 64 + (threadIdx.x >> 2);
        int s   = threadIdx.x & 3;        // lane covers dims [s*16, s*16+16)

        const float4* e4 = reinterpret_cast<const float4*>(emb) + (size_t)row * 16;
        float4 a = ldcs4(e4 + s * 4 + 0);   // evict-first streaming reads
        float4 b = ldcs4(e4 + s * 4 + 1);
        float4 c = ldcs4(e4 + s * 4 + 2);
        float4 d = ldcs4(e4 + s * 4 + 3);

        float p = a.x*a.x + a.y*a.y + a.z*a.z + a.w*a.w
                + b.x*b.x + b.y*b.y + b.z*b.z + b.w*b.w
                + c.x*c.x + c.y*c.y + c.z*c.z + c.w*c.w
                + d.x*d.x + d.y*d.y + d.z*d.z + d.w*d.w;
        float am = fmaxf(fmaxf(fmaxf(fabsf(a.x), fabsf(a.y)),
                               fmaxf(fabsf(a.z), fabsf(a.w))),
                   fmaxf(fmaxf(fabsf(b.x), fabsf(b.y)),
                         fmaxf(fabsf(b.z), fabsf(b.w))));
        am = fmaxf(am, fmaxf(fmaxf(fabsf(c.x), fabsf(c.y)),
                             fmaxf(fabsf(c.z), fabsf(c.w))));
        am = fmaxf(am, fmaxf(fmaxf(fabsf(d.x), fabsf(d.y)),
                             fmaxf(fabsf(d.z), fabsf(d.w))));
        #pragma unroll
        for (int m = 2; m; m >>= 1) {
            p  += __shfl_xor_sync(0xffffffffu, p, m);
            am  = fmaxf(am, __shfl_xor_sync(0xffffffffu, am, m));
        }

        float rinv = rsqrtf(fmaxf(p, 1e-36f));
        float un   = fmaxf(p * rinv, EPS);
        float f    = tanh_approx(un) * rinv;   // tail = f * u
        float sc   = f * am;                   // max |tail_i|
        float fi   = 127.f * f / fmaxf(sc, 1e-30f);

        uint4 o;
        o.x = pack4(a.x, a.y, a.z, a.w, fi);
        o.y = pack4(b.x, b.y, b.z, b.w, fi);
        o.z = pack4(c.x, c.y, c.z, c.w, fi);
        o.w = pack4(d.x, d.y, d.z, d.w, fi);
        g_row[(size_t)row * 8 + s] = o;

        if (s == 0) {
            float t  = tanh_approx(un);
            float t2 = t * t;
            float4 meta = make_float4(t2, __logf(fmaxf(1.f - t2, EPS)),
                                      __ldcs(bias_tail + row), sc);
            g_row[(size_t)row * 8 + 4] = *reinterpret_cast<uint4*>(&meta);
        }
    } else {
        // ---- head path: 1 warp per b-row (8 rows / block) ----
        int b    = (blockIdx.x - TAIL_BLOCKS) * 8 + (threadIdx.x >> 5);
        int lane = threadIdx.x & 31;
        int u = u_idx[b];
        int r = r_idx[b];

        float2 h  = expmap0_w(reinterpret_cast<const float2*>(emb + (size_t)u * 64)[lane]);
        float2 y1 = expmap0_w(reinterpret_cast<const float2*>(rb1 + (size_t)r * 64)[lane]);
        h = mobius_w(h, y1);

        float2 g  = reinterpret_cast<const float2*>(rel_diag + (size_t)r * 64)[lane];
        float gri = rsqrtf(fmaxf(g.x * g.x + g.y * g.y, 1e-36f));
        float gx = g.x * gri, gy = g.y * gri;
        float2 rot = make_float2(gx * h.x - gy * h.y, gy * h.x + gx * h.y);

        float2 y2 = expmap0_w(reinterpret_cast<const float2*>(rb2 + (size_t)r * 64)[lane]);
        h = mobius_w(rot, y2);

        float hh = wsum32(h.x * h.x + h.y * h.y);
        float sh = fmaxf(wmax32(fmaxf(fabsf(h.x), fabsf(h.y))), 1e-30f);
        float inv = 127.f / sh;

        int q0 = __float2int_rn(h.x * inv);
        int q1 = __float2int_rn(h.y * inv);
        unsigned pk = (q0 & 0xFF) | ((q1 & 0xFF) << 8);
        unsigned other = __shfl_xor_sync(0xffffffffu, pk, 1);
        if ((lane & 1) == 0)
            g_headq[b * 16 + (lane >> 1)] = (pk & 0xFFFFu) | (other << 16);

        if (lane == 0) {
            float sg = 1.f / (1.f + __expf(-sigma[r]));
            float A  = MARGIN + bias_head[u]
                     + (1.f - sg) * __logf(fmaxf(1.f - hh, EPS));
            g_rowc[b] = make_float4(A, sg, hh, 2.f * sh / 16129.f);
        }
    }
}

// ---------------- scoring (hot loop) ------------------------------
// Warp = 32 candidates = 4 sets of 8; 4-lane group per element.
// Lane (g,q):
//   - 4 broadcast idx LDGs (one per set)
//   - 4 dims gathers (uint4, chunk q of set j's candidate) — all lanes
//   - ONE meta LDG.128: lane q loads meta of ITS set q  (32 elems/inst)
//   - 16 dp4a, 8 shfl (2-level group reduce -> all I's on every lane)
//   - lane q selects I[q], runs epilogue for set q, one coalesced
//     STG.32 (contiguous 128B across the warp). Zero predication.
__global__ void __launch_bounds__(128) score_kernel(
    const int* __restrict__ v_idx, float* __restrict__ out)
{
    int w    = threadIdx.x >> 5;
    int gw   = blockIdx.x * 4 + w;       // global warp id
    int b    = gw >> 5;                  // b-row (32 warps per row)
    int seg  = gw & 31;
    int lane = threadIdx.x & 31;
    int g    = lane >> 2;                // group 0..7
    int q    = lane & 3;                 // slot in group

    int cbase = seg * 32;
    const int* vrow = v_idx + b * NC;
    float*     orow = out + b * NC;

    // ---- 4 broadcast idx loads (one candidate per set for group g) ----
    int v0 = __ldg(vrow + cbase + g);
    int v1 = __ldg(vrow + cbase + 8 + g);
    int v2 = __ldg(vrow + cbase + 16 + g);
    int v3 = __ldg(vrow + cbase + 24 + g);

    uint4 hq = reinterpret_cast<const uint4*>(g_headq)[b * 4 + q];
    float4 rc = g_rowc[b];               // {A, sig, hh, 2*sh/127^2}

    const char* base = reinterpret_cast<const char*>(g_row);
    unsigned so = (unsigned)q * 16u;
    unsigned o0 = (unsigned)v0 * 128u;
    unsigned o1 = (unsigned)v1 * 128u;
    unsigned o2 = (unsigned)v2 * 128u;
    unsigned o3 = (unsigned)v3 * 128u;

    // ---- dims gathers: chunk q of each set's candidate ----
    uint4 d0 = *reinterpret_cast<const uint4*>(base + (o0 + so));
    uint4 d1 = *reinterpret_cast<const uint4*>(base + (o1 + so));
    uint4 d2 = *reinterpret_cast<const uint4*>(base + (o2 + so));
    uint4 d3 = *reinterpret_cast<const uint4*>(base + (o3 + so));

    // ---- meta for MY set (lane q -> set q): one unpredicated LDG ----
    unsigned oq = (q == 0) ? o0 : (q == 1) ? o1 : (q == 2) ? o2 : o3;
    float4 mt = *reinterpret_cast<const float4*>(base + (oq + 64u));

    // ---- integer dots ----
    int I0 = 0, I1 = 0, I2 = 0, I3 = 0;
    I0 = __dp4a((int)d0.x, (int)hq.x, I0);
    I0 = __dp4a((int)d0.y, (int)hq.y, I0);
    I0 = __dp4a((int)d0.z, (int)hq.z, I0);
    I0 = __dp4a((int)d0.w, (int)hq.w, I0);
    I1 = __dp4a((int)d1.x, (int)hq.x, I1);
    I1 = __dp4a((int)d1.y, (int)hq.y, I1);
    I1 = __dp4a((int)d1.z, (int)hq.z, I1);
    I1 = __dp4a((int)d1.w, (int)hq.w, I1);
    I2 = __dp4a((int)d2.x, (int)hq.x, I2);
    I2 = __dp4a((int)d2.y, (int)hq.y, I2);
    I2 = __dp4a((int)d2.z, (int)hq.z, I2);
    I2 = __dp4a((int)d2.w, (int)hq.w, I2);
    I3 = __dp4a((int)d3.x, (int)hq.x, I3);
    I3 = __dp4a((int)d3.y, (int)hq.y, I3);
    I3 = __dp4a((int)d3.z, (int)hq.z, I3);
    I3 = __dp4a((int)d3.w, (int)hq.w, I3);

    // ---- 2-level group reduce (all four sums land on every lane) ----
    I0 += __shfl_xor_sync(0xffffffffu, I0, 1);
    I1 += __shfl_xor_sync(0xffffffffu, I1, 1);
    I2 += __shfl_xor_sync(0xffffffffu, I2, 1);
    I3 += __shfl_xor_sync(0xffffffffu, I3, 1);
    I0 += __shfl_xor_sync(0xffffffffu, I0, 2);
    I1 += __shfl_xor_sync(0xffffffffu, I1, 2);
    I2 += __shfl_xor_sync(0xffffffffu, I2, 2);
    I3 += __shfl_xor_sync(0xffffffffu, I3, 2);

    // ---- every lane: epilogue for ITS set, one coalesced store ----
    int Iq = (q == 0) ? I0 : (q == 1) ? I1 : (q == 2) ? I2 : I3;
    float num = fmaxf(rc.z + mt.x - rc.w * mt.w * (float)Iq, EPS);
    orow[cbase + q * 8 + g] = rc.x + fmaf(rc.y, mt.y, mt.z) - __logf(num);
}

// ---------------- launch ------------------------------------------
extern "C" void kernel_launch(void* const* d_in, const int* in_sizes, int n_in,
                              void* d_out, int out_size)
{
    const int*   u_idx     = (const int*)  d_in[0];
    const int*   r_idx     = (const int*)  d_in[1];
    const int*   v_idx     = (const int*)  d_in[2];
    const float* emb       = (const float*)d_in[3];
    const float* rel_diag  = (const float*)d_in[4];
    const float* rb1       = (const float*)d_in[5];
    const float* rb2       = (const float*)d_in[6];
    const float* bias_head = (const float*)d_in[7];
    const float* bias_tail = (const float*)d_in[8];
    const float* sigma     = (const float*)d_in[9];
    float* out = (float*)d_out;

    prep_kernel<<<TAIL_BLOCKS + HEAD_BLOCKS, 256>>>(
        u_idx, r_idx, emb, rel_diag, rb1, rb2, bias_head, bias_tail, sigma);
    // 1M elements / (4 warps * 32 elem) = 8192 blocks
    score_kernel<<<(BQ * NC) / 128, 128>>>(v_idx, out);
}